// round 8
// baseline (speedup 1.0000x reference)
#include <cuda_runtime.h>
#include <cuda_bf16.h>
#include <cstdint>

#define HNUM 112
#define WNUM 112
#define HW   12544      // 112*112
#define BNUM 2
#define CIN  256
#define CMID 128
#define DNUM 49
#define RAD  3

#define NT 128          // pixel (N) tile in GEMM
#define KC 64           // K chunk

#if defined(__CUDA_ARCH_FEAT_SM103_ALL) || defined(__CUDA_ARCH_FEAT_SM100_ALL) || defined(__CUDA_ARCH_FEAT_SM101_ALL)
#define HAS_TCGEN05 1
#endif

// -------- scratch (no allocations allowed) --------
__device__ __nv_bfloat16 g_Ah[2][CMID * CIN];          // [tensor][m][k] bf16 hi
__device__ __nv_bfloat16 g_Al[2][CMID * CIN];          // [tensor][m][k] bf16 lo
__device__ float g_qk[2][(size_t)BNUM * HW * CMID];    // [tensor][b*HW][128], l2-normalized

// ================= helpers =================
__device__ __forceinline__ uint32_t smem_u32(const void* p) {
    uint32_t a;
    asm("{ .reg .u64 t; cvta.to.shared.u64 t, %1; cvt.u32.u64 %0, t; }" : "=r"(a) : "l"(p));
    return a;
}
#define SW128(o) ((o) ^ (((o) >> 3) & 0x70))

#define CVT_BF16X2(res, a, b) \
    asm("cvt.rn.satfinite.bf16x2.f32 %0, %1, %2;" : "=r"(res) : "f"(b), "f"(a))

#ifdef HAS_TCGEN05
__device__ __forceinline__ uint32_t elect_one() {
    uint32_t pred;
    asm volatile("{ .reg .pred p; elect.sync _|p, 0xFFFFFFFF; selp.b32 %0, 1, 0, p; }" : "=r"(pred));
    return pred;
}

static constexpr uint64_t DESC_BASE_SW128 =
    (uint64_t(2) << 61) | (uint64_t(1) << 46) | (uint64_t(64) << 32) | (uint64_t(1) << 16);
__device__ __forceinline__ uint64_t make_desc(uint32_t addr) {
    return DESC_BASE_SW128 | ((uint64_t)(addr >> 4) & 0x3FFF);
}

// idesc: dtype=F32, atype=btype=BF16, N=128, M=128
static constexpr uint32_t GEMM_IDESC =
    (1u << 4) | (1u << 7) | (1u << 10) | ((128u / 8) << 17) | ((128u / 16) << 24);

__device__ __forceinline__ void mma_f16_ss(uint32_t d, uint64_t ad, uint64_t bd,
                                           uint32_t idesc, uint32_t en) {
    asm volatile(
        "{\n\t.reg .pred p;\n\t"
        "setp.ne.u32 p, %4, 0;\n\t"
        "tcgen05.mma.cta_group::1.kind::f16 [%0], %1, %2, %3, {%5,%5,%5,%5}, p;\n\t}"
        :: "r"(d), "l"(ad), "l"(bd), "r"(idesc), "r"(en), "r"(0u) : "memory");
}

#define TC_ALLOC(sm_addr, ncols) \
    asm volatile("tcgen05.alloc.cta_group::1.sync.aligned.shared::cta.b32 [%0], %1;" \
                 :: "r"(sm_addr), "r"((uint32_t)(ncols)) : "memory")
#define TC_DEALLOC(tm, ncols) \
    asm volatile("tcgen05.dealloc.cta_group::1.sync.aligned.b32 %0, %1;" :: "r"(tm), "r"((uint32_t)(ncols)))
#define TC_RELINQ() asm volatile("tcgen05.relinquish_alloc_permit.cta_group::1.sync.aligned;")
#define TC_COMMIT(mbar) \
    asm volatile("tcgen05.commit.cta_group::1.mbarrier::arrive::one.shared::cluster.b64 [%0];" \
                 :: "r"(mbar) : "memory")
#define TC_FENCE_AFTER()  asm volatile("tcgen05.fence::after_thread_sync;" ::: "memory")
#define TC_FENCE_BEFORE() asm volatile("tcgen05.fence::before_thread_sync;" ::: "memory")
#define TC_WAIT_LD()      asm volatile("tcgen05.wait::ld.sync.aligned;" ::: "memory")
// generic-proxy smem writes -> async-proxy (tcgen05 MMA) visibility. REQUIRED.
#define FENCE_PROXY_ASYNC() asm volatile("fence.proxy.async.shared::cta;" ::: "memory")

#define MBAR_INIT(a, n) \
    asm volatile("mbarrier.init.shared.b64 [%0], %1;" :: "r"(a), "r"((uint32_t)(n)) : "memory")

#define MBAR_WAIT(mbar_addr, par) do {                                              \
    uint32_t _m = (mbar_addr), _p = (par), _done;                                   \
    asm volatile("{ .reg .pred p; mbarrier.try_wait.parity.acquire.cta.shared::cta.b64 p, [%1], %2; selp.b32 %0, 1, 0, p; }" \
        : "=r"(_done) : "r"(_m), "r"(_p) : "memory");                               \
    if (!_done) {                                                                   \
        asm volatile("{ .reg .pred P1; WL_%=: mbarrier.try_wait.parity.acquire.cta.shared::cta.b64 P1, [%0], %1, 0x989680; @P1 bra.uni WD_%=; bra.uni WL_%=; WD_%=: }" \
            :: "r"(_m), "r"(_p) : "memory");                                        \
    }                                                                               \
} while (0)

#define LDTM_X32(r, addr) \
    asm volatile("tcgen05.ld.sync.aligned.32x32b.x32.b32 " \
        "{%0,%1,%2,%3,%4,%5,%6,%7,%8,%9,%10,%11,%12,%13,%14,%15," \
        "%16,%17,%18,%19,%20,%21,%22,%23,%24,%25,%26,%27,%28,%29,%30,%31}, [%32];" \
        : "=r"((r)[0]),"=r"((r)[1]),"=r"((r)[2]),"=r"((r)[3]),"=r"((r)[4]),"=r"((r)[5]),"=r"((r)[6]),"=r"((r)[7]), \
          "=r"((r)[8]),"=r"((r)[9]),"=r"((r)[10]),"=r"((r)[11]),"=r"((r)[12]),"=r"((r)[13]),"=r"((r)[14]),"=r"((r)[15]), \
          "=r"((r)[16]),"=r"((r)[17]),"=r"((r)[18]),"=r"((r)[19]),"=r"((r)[20]),"=r"((r)[21]),"=r"((r)[22]),"=r"((r)[23]), \
          "=r"((r)[24]),"=r"((r)[25]),"=r"((r)[26]),"=r"((r)[27]),"=r"((r)[28]),"=r"((r)[29]),"=r"((r)[30]),"=r"((r)[31]) \
        : "r"(addr))
#endif // HAS_TCGEN05

// ---------------------------------------------------------------
// K0: split Wq/Wk into bf16 hi/lo ([m][k], k contiguous)
// ---------------------------------------------------------------
__global__ void k_prep(const float* __restrict__ Wq, const float* __restrict__ Wk) {
    int id = blockIdx.x * blockDim.x + threadIdx.x;
    if (id < CMID * CIN) {
        float a = Wq[id];
        __nv_bfloat16 h = __float2bfloat16_rn(a);
        g_Ah[0][id] = h;
        g_Al[0][id] = __float2bfloat16_rn(a - __bfloat162float(h));
        float b = Wk[id];
        __nv_bfloat16 h2 = __float2bfloat16_rn(b);
        g_Ah[1][id] = h2;
        g_Al[1][id] = __float2bfloat16_rn(b - __bfloat162float(h2));
    }
}

// ---------------------------------------------------------------
// K1: projection GEMM + fused per-pixel l2norm.
// Single 128-col TMEM accumulator; proxy-fenced staging; B staged as
// packed bf16x2 b32 stores (half the STS stream vs b16).
// ---------------------------------------------------------------
#define GEMM_SMEM 67584

__global__ __launch_bounds__(256) void k_gemm(const float* __restrict__ phi_cur,
                                              const float* __restrict__ phi_rnd) {
    extern __shared__ char smraw[];
    const int t = threadIdx.x;
    const int tsel = blockIdx.z, b = blockIdx.y;
    const int p0 = blockIdx.x * NT;

    const float* __restrict__ X = (tsel ? phi_rnd : phi_cur) + (size_t)b * CIN * HW;
    const __nv_bfloat16* __restrict__ Agh = g_Ah[tsel];
    const __nv_bfloat16* __restrict__ Agl = g_Al[tsel];

#ifdef HAS_TCGEN05
    const uint32_t sraw = smem_u32(smraw);
    const uint32_t sb = (sraw + 1023) & ~1023u;
    float* tb = (float*)(smraw + (sb - sraw));        // epilogue transpose buffer

    const uint32_t Ah = sb, Al = sb + 16384, Bh = sb + 32768, Bl = sb + 49152;
    const uint32_t HDR = sb + 66304;                  // tmem ptr
    const uint32_t MBAR = HDR + 8;
    const int wid = t >> 5;

    if (t == 0) MBAR_INIT(MBAR, 1);
    if (wid == 0) TC_ALLOC(HDR, 128);
    __syncthreads();
    uint32_t tmem;
    asm volatile("ld.shared.b32 %0, [%1];" : "=r"(tmem) : "r"(HDR));

    for (int ch = 0; ch < CIN / KC; ch++) {
        const int c0 = ch * KC;
        // ---- stage A chunk [128 m][64 k] bf16 hi/lo, SW128 ----
#pragma unroll
        for (int i = 0; i < 16; i++) {
            int id = t + i * 256;              // 0..4095 u32 (2 bf16 each)
            int m = id >> 5, q = id & 31;
            uint32_t vh = *(const uint32_t*)(Agh + m * CIN + c0 + q * 2);
            uint32_t vl = *(const uint32_t*)(Agl + m * CIN + c0 + q * 2);
            uint32_t off = SW128((uint32_t)(m * 128 + q * 4));
            asm volatile("st.shared.b32 [%0], %1;" :: "r"(Ah + off), "r"(vh));
            asm volatile("st.shared.b32 [%0], %1;" :: "r"(Al + off), "r"(vl));
        }
        // ---- stage B chunk: X[c0..+64][p0..+128] -> [p][k] bf16x2 hi/lo, SW128 ----
#pragma unroll
        for (int i = 0; i < 16; i++) {
            int id = t + i * 256;              // 0..4095  (pairs of c)
            int p = id & 127, cp = id >> 7;    // cp 0..31
            int c = cp * 2;
            float x0 = X[(size_t)(c0 + c) * HW + p0 + p];
            float x1 = X[(size_t)(c0 + c + 1) * HW + p0 + p];
            uint32_t hp;
            CVT_BF16X2(hp, x0, x1);            // lo=bf16(x0), hi=bf16(x1)
            float h0f = __uint_as_float(hp << 16);
            float h1f = __uint_as_float(hp & 0xffff0000u);
            float l0 = x0 - h0f, l1 = x1 - h1f;
            uint32_t lp;
            CVT_BF16X2(lp, l0, l1);
            uint32_t off = SW128((uint32_t)(p * 128 + c * 2));
            asm volatile("st.shared.b32 [%0], %1;" :: "r"(Bh + off), "r"(hp));
            asm volatile("st.shared.b32 [%0], %1;" :: "r"(Bl + off), "r"(lp));
        }
        // make this thread's generic-proxy smem writes visible to the async proxy
        FENCE_PROXY_ASYNC();
        __syncthreads();

        if (wid == 0 && elect_one()) {
            uint64_t adh = make_desc(Ah), adl = make_desc(Al);
            uint64_t bdh = make_desc(Bh), bdl = make_desc(Bl);
#pragma unroll
            for (int ks = 0; ks < 4; ks++) {   // K=16 per MMA
                uint32_t en0 = (ch > 0 || ks > 0) ? 1u : 0u;
                mma_f16_ss(tmem, adh + ks * 2, bdh + ks * 2, GEMM_IDESC, en0);
                mma_f16_ss(tmem, adh + ks * 2, bdl + ks * 2, GEMM_IDESC, 1u);
                mma_f16_ss(tmem, adl + ks * 2, bdh + ks * 2, GEMM_IDESC, 1u);
            }
            TC_COMMIT(MBAR);
        }
        MBAR_WAIT(MBAR, ch & 1);
    }

    // ---- epilogue: LDTM -> smem transpose -> per-pixel l2norm -> pixel-major out ----
    TC_FENCE_AFTER();
    const int sub = wid & 3, half = wid >> 2;
    const int lane = t & 31;
    const int m = sub * 32 + lane;

    uint32_t d0[32], d1[32];
    LDTM_X32(d0, tmem + half * 64);
    LDTM_X32(d1, tmem + half * 64 + 32);
    TC_WAIT_LD();
    TC_FENCE_BEFORE();
    __syncthreads();     // stage buffers dead; tb overwrites them

#pragma unroll
    for (int j = 0; j < 32; j++) tb[m * 129 + half * 64 + j]      = __uint_as_float(d0[j]);
#pragma unroll
    for (int j = 0; j < 32; j++) tb[m * 129 + half * 64 + 32 + j] = __uint_as_float(d1[j]);
    __syncthreads();

    {
        const int p = t >> 1, hh = t & 1;
        float s = 0.f;
#pragma unroll
        for (int mm = 0; mm < 64; mm++) {
            float v = tb[(hh * 64 + mm) * 129 + p];
            s += v * v;
        }
        s += __shfl_xor_sync(0xffffffffu, s, 1);
        float sc = 1.f / fmaxf(sqrtf(s), 1e-12f);
        float* OUT = g_qk[tsel] + ((size_t)b * HW + p0 + p) * CMID + hh * 64;
#pragma unroll
        for (int j = 0; j < 64; j += 4) {
            float4 v;
            v.x = tb[(hh * 64 + j + 0) * 129 + p] * sc;
            v.y = tb[(hh * 64 + j + 1) * 129 + p] * sc;
            v.z = tb[(hh * 64 + j + 2) * 129 + p] * sc;
            v.w = tb[(hh * 64 + j + 3) * 129 + p] * sc;
            *(float4*)(OUT + j) = v;
        }
    }
    __syncthreads();
    if (wid == 0) {
        TC_RELINQ();
        TC_DEALLOC(tmem, 128);
    }
#else
    // ---------- SIMT fallback (generic gencode pass; not selected on GB300) ----------
    float* Ws = (float*)smraw;                 // [16][128]
    float* Xs = Ws + 16 * 128;                 // [16][128]
    float* red = Xs + 16 * 128;                // [16][128]
    float* scale_s = red + 16 * 128;           // [128]

    const int to = t >> 4, tp = t & 15;
    const int m0 = to * 8, q0 = tp * 8;

    float acc[8][8];
#pragma unroll
    for (int i = 0; i < 8; i++)
#pragma unroll
        for (int j = 0; j < 8; j++) acc[i][j] = 0.f;

    for (int c0 = 0; c0 < CIN; c0 += 16) {
#pragma unroll
        for (int i = 0; i < 8; i++) {
            int id = t + i * 256;              // 0..2047
            int c = id >> 7, m = id & 127;
            Ws[c * 128 + m] = __bfloat162float(Agh[m * CIN + c0 + c]) +
                              __bfloat162float(Agl[m * CIN + c0 + c]);
            Xs[c * 128 + m] = X[(size_t)(c0 + c) * HW + p0 + m];
        }
        __syncthreads();
#pragma unroll
        for (int cc = 0; cc < 16; cc++) {
            float wv[8], xv[8];
#pragma unroll
            for (int i = 0; i < 8; i++) wv[i] = Ws[cc * 128 + m0 + i];
#pragma unroll
            for (int j = 0; j < 8; j++) xv[j] = Xs[cc * 128 + q0 + j];
#pragma unroll
            for (int i = 0; i < 8; i++)
#pragma unroll
                for (int j = 0; j < 8; j++) acc[i][j] += wv[i] * xv[j];
        }
        __syncthreads();
    }

#pragma unroll
    for (int j = 0; j < 8; j++) {
        float s = 0.f;
#pragma unroll
        for (int i = 0; i < 8; i++) s += acc[i][j] * acc[i][j];
        red[to * 128 + q0 + j] = s;
    }
    __syncthreads();
    if (t < 128) {
        float n = 0.f;
#pragma unroll
        for (int g = 0; g < 16; g++) n += red[g * 128 + t];
        scale_s[t] = 1.f / fmaxf(sqrtf(n), 1e-12f);
    }
    __syncthreads();

#pragma unroll
    for (int j = 0; j < 8; j++) {
        float sc = scale_s[q0 + j];
        float* dst = g_qk[tsel] + ((size_t)b * HW + p0 + q0 + j) * CMID + m0;
#pragma unroll
        for (int i = 0; i < 8; i++) dst[i] = acc[i][j] * sc;
    }
#endif
}

// ---------------------------------------------------------------
// K2 (fused): local correlation -> smem -> Wv matvec + geometry +
// softmax + du/dv/conf. corr never touches gmem; k_final eliminated.
// Phase 1: 64 px x 4 d-groups (d = grp+4k), halo-tiled k in smem.
// Phase 2: 4 threads/pixel, thread q owns logits [16q,16q+16).
// ---------------------------------------------------------------
__global__ __launch_bounds__(256) void k_corr_final(const float* __restrict__ P_cur,
                                                    const float* __restrict__ P_rnd,
                                                    const float* __restrict__ Wv,
                                                    const float* __restrict__ bv,
                                                    const float* __restrict__ gamma_p,
                                                    float* __restrict__ out) {
    const int tx = blockIdx.x, ty = blockIdx.y, b = blockIdx.z;
    const int t   = threadIdx.x;

    __shared__ float ks[16][196];      // halo tile per 16-ch chunk
    __shared__ float corr_s[64 * 53];  // [pix][d], stride 53 (conflict-free)
    __shared__ float Wvt[49 * 64];     // [d][e], e padded to 64 (pad = 0)
    __shared__ float bvs[64];

    // stage Wv transpose + bv (used in phase 2)
    for (int id = t; id < 49 * 64; id += 256) {
        int d = id >> 6, e = id & 63;
        Wvt[id] = (e < 49) ? Wv[e * 49 + d] : 0.f;
    }
    if (t < 64) bvs[t] = (t < 49) ? bv[t] : -3.0e38f;

    // ===== phase 1: correlation =====
    const int pix = t & 63;
    const int grp = t >> 6;
    const int px  = pix & 7;
    const int py  = pix >> 3;

    const float* __restrict__ Q = g_qk[0] + (size_t)b * HW * CMID;
    const float* __restrict__ K = g_qk[1] + (size_t)b * HW * CMID;

    const int gx = tx * 8 + px;
    const int gy = ty * 8 + py;
    const int pb = py * 14 + px;

    int addr[13];
#pragma unroll
    for (int k = 0; k < 13; k++) {
        int d  = grp + 4 * k;
        int dd = (d < DNUM) ? d : 0;
        addr[k] = pb + (dd / 7) * 14 + (dd % 7);
    }

    float acc[13];
#pragma unroll
    for (int k = 0; k < 13; k++) acc[k] = 0.f;

    const float* __restrict__ qptr = Q + (size_t)(gy * WNUM + gx) * CMID;

    for (int c0 = 0; c0 < CMID; c0 += 16) {
#pragma unroll
        for (int i = 0; i < 4; i++) {
            int id = t + i * 256;
            if (id < 784) {
                int hp = id >> 2;
                int cv = id & 3;
                int hy = hp / 14, hx = hp - hy * 14;
                int sy = ty * 8 + hy - RAD;
                int sx = tx * 8 + hx - RAD;
                float4 v = make_float4(0.f, 0.f, 0.f, 0.f);
                if ((unsigned)sy < (unsigned)HNUM && (unsigned)sx < (unsigned)WNUM)
                    v = *(const float4*)(K + (size_t)(sy * WNUM + sx) * CMID + c0 + cv * 4);
                ks[cv * 4 + 0][hp] = v.x;
                ks[cv * 4 + 1][hp] = v.y;
                ks[cv * 4 + 2][hp] = v.z;
                ks[cv * 4 + 3][hp] = v.w;
            }
        }
        __syncthreads();

        float qr[16];
#pragma unroll
        for (int i = 0; i < 4; i++)
            *(float4*)&qr[i * 4] = *(const float4*)(qptr + c0 + i * 4);

#pragma unroll
        for (int cc = 0; cc < 16; cc++) {
            float qc = qr[cc];
#pragma unroll
            for (int k = 0; k < 13; k++)
                acc[k] += qc * ks[cc][addr[k]];
        }
        __syncthreads();
    }

#pragma unroll
    for (int k = 0; k < 13; k++) {
        int d = grp + 4 * k;
        if (d < DNUM)
            corr_s[pix * 53 + d] = acc[k];
    }
    __syncthreads();

    // ===== phase 2: Wv matvec + geometry + softmax =====
    const int q  = t & 3;
    const int pl = t >> 2;                 // pixel within tile
    const int px2 = pl & 7, py2 = pl >> 3;
    const int gx2 = tx * 8 + px2;
    const int gy2 = ty * 8 + py2;
    const int hw  = gy2 * WNUM + gx2;
    const int pixg = b * HW + hw;
    const float gamma = *gamma_p;
    const int e0 = q * 16;

    const float* __restrict__ Pc = P_cur + (size_t)b * 3 * HW;
    const float* __restrict__ Pr = P_rnd + (size_t)b * 3 * HW;
    const float pcx = Pc[hw], pcy = Pc[HW + hw], pcz = Pc[2 * HW + hw];

    float l[16];
#pragma unroll
    for (int i = 0; i < 16; i++) {
        int e = e0 + i;
        if (e < 49) {
            int iy = e / 7, ix = e - iy * 7;
            int sy = gy2 + iy - RAD, sx = gx2 + ix - RAD;
            float prx = 0.f, pry = 0.f, prz = 0.f;
            if ((unsigned)sy < (unsigned)HNUM && (unsigned)sx < (unsigned)WNUM) {
                int o = sy * WNUM + sx;
                prx = Pr[o]; pry = Pr[HW + o]; prz = Pr[2 * HW + o];
            }
            float dx = pcx - prx, dy = pcy - pry, dz = pcz - prz;
            float ds = dx * dx + dy * dy + dz * dz;
            float dist = sqrtf(fmaxf(ds, 1e-12f));
            l[i] = bvs[e] + gamma * (-dist - 0.5f * fabsf(dz));
        } else {
            l[i] = -3.0e38f;
        }
    }

    for (int d = 0; d < 49; d++) {
        float cd = corr_s[pl * 53 + d];
        const float* wr = &Wvt[d * 64 + e0];
#pragma unroll
        for (int v4 = 0; v4 < 4; v4++) {
            float4 wv = *(const float4*)(wr + v4 * 4);
            l[v4 * 4 + 0] += wv.x * cd;
            l[v4 * 4 + 1] += wv.y * cd;
            l[v4 * 4 + 2] += wv.z * cd;
            l[v4 * 4 + 3] += wv.w * cd;
        }
    }

    float m = l[0];
#pragma unroll
    for (int i = 1; i < 16; i++) m = fmaxf(m, l[i]);
    m = fmaxf(m, __shfl_xor_sync(0xffffffffu, m, 1));
    m = fmaxf(m, __shfl_xor_sync(0xffffffffu, m, 2));

    float S = 0.f, du = 0.f, dv = 0.f;
#pragma unroll
    for (int i = 0; i < 16; i++) {
        int e = e0 + i;
        float ex = (e < 49) ? __expf(l[i] - m) : 0.f;
        S  += ex;
        du += ex * (float)(e % 7 - 3);
        dv += ex * (float)(e / 7 - 3);
    }
    S  += __shfl_xor_sync(0xffffffffu, S, 1);
    S  += __shfl_xor_sync(0xffffffffu, S, 2);
    du += __shfl_xor_sync(0xffffffffu, du, 1);
    du += __shfl_xor_sync(0xffffffffu, du, 2);
    dv += __shfl_xor_sync(0xffffffffu, dv, 1);
    dv += __shfl_xor_sync(0xffffffffu, dv, 2);

    if (q == 0) {
        float inv = 1.f / S;
        out[pixg]                 = du * inv;
        out[BNUM * HW + pixg]     = dv * inv;
        out[2 * BNUM * HW + pixg] = inv;   // conf = exp(m-m)/S
    }
}

// ---------------------------------------------------------------
extern "C" void kernel_launch(void* const* d_in, const int* in_sizes, int n_in,
                              void* d_out, int out_size) {
    const float* phi_cur = (const float*)d_in[0];
    const float* phi_rnd = (const float*)d_in[1];
    const float* P_cur   = (const float*)d_in[2];
    const float* P_rnd   = (const float*)d_in[3];
    const float* Wq      = (const float*)d_in[4];
    const float* Wk      = (const float*)d_in[5];
    const float* Wv      = (const float*)d_in[6];
    const float* bv      = (const float*)d_in[7];
    const float* gamma   = (const float*)d_in[8];
    float* out = (float*)d_out;

    cudaFuncSetAttribute(k_gemm, cudaFuncAttributeMaxDynamicSharedMemorySize, GEMM_SMEM);

    k_prep<<<128, 256>>>(Wq, Wk);
    k_gemm<<<dim3(HW / NT, BNUM, 2), 256, GEMM_SMEM>>>(phi_cur, phi_rnd);
    k_corr_final<<<dim3(WNUM / 8, HNUM / 8, BNUM), 256>>>(P_cur, P_rnd, Wv, bv, gamma, out);
}

// round 9
// speedup vs baseline: 1.3940x; 1.3940x over previous
#include <cuda_runtime.h>
#include <cuda_bf16.h>
#include <cstdint>

#define HNUM 112
#define WNUM 112
#define HW   12544      // 112*112
#define BNUM 2
#define CIN  256
#define CMID 128
#define DNUM 49
#define RAD  3

#define NT 128          // pixel (N) tile in GEMM
#define KC 64           // K chunk

#if defined(__CUDA_ARCH_FEAT_SM103_ALL) || defined(__CUDA_ARCH_FEAT_SM100_ALL) || defined(__CUDA_ARCH_FEAT_SM101_ALL)
#define HAS_TCGEN05 1
#endif

// -------- scratch (no allocations allowed) --------
__device__ __nv_bfloat16 g_Ah[2][CMID * CIN];          // [tensor][m][k] bf16 hi
__device__ __nv_bfloat16 g_Al[2][CMID * CIN];          // [tensor][m][k] bf16 lo
__device__ float g_qk[2][(size_t)BNUM * HW * CMID];    // [tensor][b*HW][128], l2-normalized
__device__ float g_corr[(size_t)BNUM * DNUM * HW];     // [b][d][hw]

// ================= helpers =================
__device__ __forceinline__ uint32_t smem_u32(const void* p) {
    uint32_t a;
    asm("{ .reg .u64 t; cvta.to.shared.u64 t, %1; cvt.u32.u64 %0, t; }" : "=r"(a) : "l"(p));
    return a;
}
#define SW128(o) ((o) ^ (((o) >> 3) & 0x70))

#ifdef HAS_TCGEN05
__device__ __forceinline__ uint32_t elect_one() {
    uint32_t pred;
    asm volatile("{ .reg .pred p; elect.sync _|p, 0xFFFFFFFF; selp.b32 %0, 1, 0, p; }" : "=r"(pred));
    return pred;
}

static constexpr uint64_t DESC_BASE_SW128 =
    (uint64_t(2) << 61) | (uint64_t(1) << 46) | (uint64_t(64) << 32) | (uint64_t(1) << 16);
__device__ __forceinline__ uint64_t make_desc(uint32_t addr) {
    return DESC_BASE_SW128 | ((uint64_t)(addr >> 4) & 0x3FFF);
}

// idesc: dtype=F32, atype=btype=BF16, N=128, M=128
static constexpr uint32_t GEMM_IDESC =
    (1u << 4) | (1u << 7) | (1u << 10) | ((128u / 8) << 17) | ((128u / 16) << 24);

__device__ __forceinline__ void mma_f16_ss(uint32_t d, uint64_t ad, uint64_t bd,
                                           uint32_t idesc, uint32_t en) {
    asm volatile(
        "{\n\t.reg .pred p;\n\t"
        "setp.ne.u32 p, %4, 0;\n\t"
        "tcgen05.mma.cta_group::1.kind::f16 [%0], %1, %2, %3, {%5,%5,%5,%5}, p;\n\t}"
        :: "r"(d), "l"(ad), "l"(bd), "r"(idesc), "r"(en), "r"(0u) : "memory");
}

#define TC_ALLOC(sm_addr, ncols) \
    asm volatile("tcgen05.alloc.cta_group::1.sync.aligned.shared::cta.b32 [%0], %1;" \
                 :: "r"(sm_addr), "r"((uint32_t)(ncols)) : "memory")
#define TC_DEALLOC(tm, ncols) \
    asm volatile("tcgen05.dealloc.cta_group::1.sync.aligned.b32 %0, %1;" :: "r"(tm), "r"((uint32_t)(ncols)))
#define TC_RELINQ() asm volatile("tcgen05.relinquish_alloc_permit.cta_group::1.sync.aligned;")
#define TC_COMMIT(mbar) \
    asm volatile("tcgen05.commit.cta_group::1.mbarrier::arrive::one.shared::cluster.b64 [%0];" \
                 :: "r"(mbar) : "memory")
#define TC_FENCE_AFTER()  asm volatile("tcgen05.fence::after_thread_sync;" ::: "memory")
#define TC_FENCE_BEFORE() asm volatile("tcgen05.fence::before_thread_sync;" ::: "memory")
#define TC_WAIT_LD()      asm volatile("tcgen05.wait::ld.sync.aligned;" ::: "memory")
// generic-proxy smem writes -> async-proxy (tcgen05 MMA) visibility. REQUIRED.
#define FENCE_PROXY_ASYNC() asm volatile("fence.proxy.async.shared::cta;" ::: "memory")

#define MBAR_INIT(a, n) \
    asm volatile("mbarrier.init.shared.b64 [%0], %1;" :: "r"(a), "r"((uint32_t)(n)) : "memory")

#define MBAR_WAIT(mbar_addr, par) do {                                              \
    uint32_t _m = (mbar_addr), _p = (par), _done;                                   \
    asm volatile("{ .reg .pred p; mbarrier.try_wait.parity.acquire.cta.shared::cta.b64 p, [%1], %2; selp.b32 %0, 1, 0, p; }" \
        : "=r"(_done) : "r"(_m), "r"(_p) : "memory");                               \
    if (!_done) {                                                                   \
        asm volatile("{ .reg .pred P1; WL_%=: mbarrier.try_wait.parity.acquire.cta.shared::cta.b64 P1, [%0], %1, 0x989680; @P1 bra.uni WD_%=; bra.uni WL_%=; WD_%=: }" \
            :: "r"(_m), "r"(_p) : "memory");                                        \
    }                                                                               \
} while (0)

#define LDTM_X32(r, addr) \
    asm volatile("tcgen05.ld.sync.aligned.32x32b.x32.b32 " \
        "{%0,%1,%2,%3,%4,%5,%6,%7,%8,%9,%10,%11,%12,%13,%14,%15," \
        "%16,%17,%18,%19,%20,%21,%22,%23,%24,%25,%26,%27,%28,%29,%30,%31}, [%32];" \
        : "=r"((r)[0]),"=r"((r)[1]),"=r"((r)[2]),"=r"((r)[3]),"=r"((r)[4]),"=r"((r)[5]),"=r"((r)[6]),"=r"((r)[7]), \
          "=r"((r)[8]),"=r"((r)[9]),"=r"((r)[10]),"=r"((r)[11]),"=r"((r)[12]),"=r"((r)[13]),"=r"((r)[14]),"=r"((r)[15]), \
          "=r"((r)[16]),"=r"((r)[17]),"=r"((r)[18]),"=r"((r)[19]),"=r"((r)[20]),"=r"((r)[21]),"=r"((r)[22]),"=r"((r)[23]), \
          "=r"((r)[24]),"=r"((r)[25]),"=r"((r)[26]),"=r"((r)[27]),"=r"((r)[28]),"=r"((r)[29]),"=r"((r)[30]),"=r"((r)[31]) \
        : "r"(addr))
#endif // HAS_TCGEN05

// ---------------------------------------------------------------
// K0: split Wq/Wk into bf16 hi/lo ([m][k], k contiguous)
// ---------------------------------------------------------------
__global__ void k_prep(const float* __restrict__ Wq, const float* __restrict__ Wk) {
    int id = blockIdx.x * blockDim.x + threadIdx.x;
    if (id < CMID * CIN) {
        float a = Wq[id];
        __nv_bfloat16 h = __float2bfloat16_rn(a);
        g_Ah[0][id] = h;
        g_Al[0][id] = __float2bfloat16_rn(a - __bfloat162float(h));
        float b = Wk[id];
        __nv_bfloat16 h2 = __float2bfloat16_rn(b);
        g_Ah[1][id] = h2;
        g_Al[1][id] = __float2bfloat16_rn(b - __bfloat162float(h2));
    }
}

// ---------------------------------------------------------------
// K1: projection GEMM + fused per-pixel l2norm.
// Single 128-col TMEM accumulator; proxy-fenced staging.
// Pipelined: next chunk's gmem loads issue into REGISTERS before the wait
// on the previous chunk's MMA -> LDG latency overlaps tensor work with a
// single smem buffer.
// ---------------------------------------------------------------
#define GEMM_SMEM 67584

__global__ __launch_bounds__(256) void k_gemm(const float* __restrict__ phi_cur,
                                              const float* __restrict__ phi_rnd) {
    extern __shared__ char smraw[];
    const int t = threadIdx.x;
    const int tsel = blockIdx.z, b = blockIdx.y;
    const int p0 = blockIdx.x * NT;

    const float* __restrict__ X = (tsel ? phi_rnd : phi_cur) + (size_t)b * CIN * HW;
    const __nv_bfloat16* __restrict__ Agh = g_Ah[tsel];
    const __nv_bfloat16* __restrict__ Agl = g_Al[tsel];

#ifdef HAS_TCGEN05
    const uint32_t sraw = smem_u32(smraw);
    const uint32_t sb = (sraw + 1023) & ~1023u;
    float* tb = (float*)(smraw + (sb - sraw));        // epilogue transpose buffer

    const uint32_t Ah = sb, Al = sb + 16384, Bh = sb + 32768, Bl = sb + 49152;
    const uint32_t HDR = sb + 66304;                  // tmem ptr
    const uint32_t MBAR = HDR + 8;
    const int wid = t >> 5;

    if (t == 0) MBAR_INIT(MBAR, 1);
    if (wid == 0) TC_ALLOC(HDR, 128);
    __syncthreads();
    uint32_t tmem;
    asm volatile("ld.shared.b32 %0, [%1];" : "=r"(tmem) : "r"(HDR));

    // per-thread indices for staging (constant over chunks)
    const int am = t >> 1;                 // unused placeholder (kept simple below)

    float    bx[32];       // prefetched X values (B tile)
    uint32_t avh[16], avl[16];  // prefetched A hi/lo packed pairs

    // ---- prefetch chunk 0 ----
#pragma unroll
    for (int i = 0; i < 16; i++) {
        int id = t + i * 256;
        int m = id >> 5, q = id & 31;
        avh[i] = *(const uint32_t*)(Agh + m * CIN + 0 + q * 2);
        avl[i] = *(const uint32_t*)(Agl + m * CIN + 0 + q * 2);
    }
#pragma unroll
    for (int i = 0; i < 32; i++) {
        int id = t + i * 256;
        int p = id & 127, c = id >> 7;
        bx[i] = X[(size_t)c * HW + p0 + p];
    }

    for (int ch = 0; ch < CIN / KC; ch++) {
        // wait for previous chunk's MMA before overwriting the buffers
        if (ch > 0) MBAR_WAIT(MBAR, (ch - 1) & 1);

        // ---- store staged chunk from registers (A hi/lo, B hi/lo) ----
#pragma unroll
        for (int i = 0; i < 16; i++) {
            int id = t + i * 256;
            int m = id >> 5, q = id & 31;
            uint32_t off = SW128((uint32_t)(m * 128 + q * 4));
            asm volatile("st.shared.b32 [%0], %1;" :: "r"(Ah + off), "r"(avh[i]));
            asm volatile("st.shared.b32 [%0], %1;" :: "r"(Al + off), "r"(avl[i]));
        }
#pragma unroll
        for (int i = 0; i < 32; i++) {
            int id = t + i * 256;
            int p = id & 127, c = id >> 7;
            float x = bx[i];
            __nv_bfloat16 h = __float2bfloat16_rn(x);
            __nv_bfloat16 l = __float2bfloat16_rn(x - __bfloat162float(h));
            uint32_t off = SW128((uint32_t)(p * 128 + c * 2));
            unsigned short hu = __bfloat16_as_ushort(h);
            unsigned short lu = __bfloat16_as_ushort(l);
            asm volatile("st.shared.b16 [%0], %1;" :: "r"(Bh + off), "h"(hu));
            asm volatile("st.shared.b16 [%0], %1;" :: "r"(Bl + off), "h"(lu));
        }
        FENCE_PROXY_ASYNC();
        __syncthreads();

        if (wid == 0 && elect_one()) {
            uint64_t adh = make_desc(Ah), adl = make_desc(Al);
            uint64_t bdh = make_desc(Bh), bdl = make_desc(Bl);
#pragma unroll
            for (int ks = 0; ks < 4; ks++) {   // K=16 per MMA
                uint32_t en0 = (ch > 0 || ks > 0) ? 1u : 0u;
                mma_f16_ss(tmem, adh + ks * 2, bdh + ks * 2, GEMM_IDESC, en0);
                mma_f16_ss(tmem, adh + ks * 2, bdl + ks * 2, GEMM_IDESC, 1u);
                mma_f16_ss(tmem, adl + ks * 2, bdh + ks * 2, GEMM_IDESC, 1u);
            }
            TC_COMMIT(MBAR);
        }

        // ---- prefetch next chunk while this chunk's MMA runs ----
        if (ch < CIN / KC - 1) {
            const int c0n = (ch + 1) * KC;
#pragma unroll
            for (int i = 0; i < 16; i++) {
                int id = t + i * 256;
                int m = id >> 5, q = id & 31;
                avh[i] = *(const uint32_t*)(Agh + m * CIN + c0n + q * 2);
                avl[i] = *(const uint32_t*)(Agl + m * CIN + c0n + q * 2);
            }
#pragma unroll
            for (int i = 0; i < 32; i++) {
                int id = t + i * 256;
                int p = id & 127, c = id >> 7;
                bx[i] = X[(size_t)(c0n + c) * HW + p0 + p];
            }
        }
    }
    MBAR_WAIT(MBAR, (CIN / KC - 1) & 1);

    // ---- epilogue: LDTM -> smem transpose -> per-pixel l2norm -> pixel-major out ----
    TC_FENCE_AFTER();
    const int sub = wid & 3, half = wid >> 2;
    const int lane = t & 31;
    const int m = sub * 32 + lane;
    (void)am;

    uint32_t d0[32], d1[32];
    LDTM_X32(d0, tmem + half * 64);
    LDTM_X32(d1, tmem + half * 64 + 32);
    TC_WAIT_LD();
    TC_FENCE_BEFORE();
    __syncthreads();     // stage buffers dead; tb overwrites them

#pragma unroll
    for (int j = 0; j < 32; j++) tb[m * 129 + half * 64 + j]      = __uint_as_float(d0[j]);
#pragma unroll
    for (int j = 0; j < 32; j++) tb[m * 129 + half * 64 + 32 + j] = __uint_as_float(d1[j]);
    __syncthreads();

    {
        const int p = t >> 1, hh = t & 1;
        float s = 0.f;
#pragma unroll
        for (int mm = 0; mm < 64; mm++) {
            float v = tb[(hh * 64 + mm) * 129 + p];
            s += v * v;
        }
        s += __shfl_xor_sync(0xffffffffu, s, 1);
        float sc = 1.f / fmaxf(sqrtf(s), 1e-12f);
        float* OUT = g_qk[tsel] + ((size_t)b * HW + p0 + p) * CMID + hh * 64;
#pragma unroll
        for (int j = 0; j < 64; j += 4) {
            float4 v;
            v.x = tb[(hh * 64 + j + 0) * 129 + p] * sc;
            v.y = tb[(hh * 64 + j + 1) * 129 + p] * sc;
            v.z = tb[(hh * 64 + j + 2) * 129 + p] * sc;
            v.w = tb[(hh * 64 + j + 3) * 129 + p] * sc;
            *(float4*)(OUT + j) = v;
        }
    }
    __syncthreads();
    if (wid == 0) {
        TC_RELINQ();
        TC_DEALLOC(tmem, 128);
    }
#else
    // ---------- SIMT fallback (generic gencode pass; not selected on GB300) ----------
    float* Ws = (float*)smraw;                 // [16][128]
    float* Xs = Ws + 16 * 128;                 // [16][128]
    float* red = Xs + 16 * 128;                // [16][128]
    float* scale_s = red + 16 * 128;           // [128]

    const int to = t >> 4, tp = t & 15;
    const int m0 = to * 8, q0 = tp * 8;

    float acc[8][8];
#pragma unroll
    for (int i = 0; i < 8; i++)
#pragma unroll
        for (int j = 0; j < 8; j++) acc[i][j] = 0.f;

    for (int c0 = 0; c0 < CIN; c0 += 16) {
#pragma unroll
        for (int i = 0; i < 8; i++) {
            int id = t + i * 256;              // 0..2047
            int c = id >> 7, m = id & 127;
            Ws[c * 128 + m] = __bfloat162float(Agh[m * CIN + c0 + c]) +
                              __bfloat162float(Agl[m * CIN + c0 + c]);
            Xs[c * 128 + m] = X[(size_t)(c0 + c) * HW + p0 + m];
        }
        __syncthreads();
#pragma unroll
        for (int cc = 0; cc < 16; cc++) {
            float wv[8], xv[8];
#pragma unroll
            for (int i = 0; i < 8; i++) wv[i] = Ws[cc * 128 + m0 + i];
#pragma unroll
            for (int j = 0; j < 8; j++) xv[j] = Xs[cc * 128 + q0 + j];
#pragma unroll
            for (int i = 0; i < 8; i++)
#pragma unroll
                for (int j = 0; j < 8; j++) acc[i][j] += wv[i] * xv[j];
        }
        __syncthreads();
    }

#pragma unroll
    for (int j = 0; j < 8; j++) {
        float s = 0.f;
#pragma unroll
        for (int i = 0; i < 8; i++) s += acc[i][j] * acc[i][j];
        red[to * 128 + q0 + j] = s;
    }
    __syncthreads();
    if (t < 128) {
        float n = 0.f;
#pragma unroll
        for (int g = 0; g < 16; g++) n += red[g * 128 + t];
        scale_s[t] = 1.f / fmaxf(sqrtf(n), 1e-12f);
    }
    __syncthreads();

#pragma unroll
    for (int j = 0; j < 8; j++) {
        float sc = scale_s[q0 + j];
        float* dst = g_qk[tsel] + ((size_t)b * HW + p0 + q0 + j) * CMID + m0;
#pragma unroll
        for (int i = 0; i < 8; i++) dst[i] = acc[i][j] * sc;
    }
#endif
}

// ---------------------------------------------------------------
// K2: local correlation. corr[b][d][hw] = sum_c q[b][hw][c]*k[b][hw+off(d)][c]
// ---------------------------------------------------------------
__global__ __launch_bounds__(256) void k_corr() {
    const int tx = blockIdx.x, ty = blockIdx.y, b = blockIdx.z;
    const int t   = threadIdx.x;
    const int pix = t & 63;
    const int grp = t >> 6;
    const int px  = pix & 7;
    const int py  = pix >> 3;

    __shared__ float ks[16][196];

    const float* __restrict__ Q = g_qk[0] + (size_t)b * HW * CMID;
    const float* __restrict__ K = g_qk[1] + (size_t)b * HW * CMID;

    const int gx = tx * 8 + px;
    const int gy = ty * 8 + py;
    const int pb = py * 14 + px;

    int addr[13];
#pragma unroll
    for (int k = 0; k < 13; k++) {
        int d  = grp + 4 * k;
        int dd = (d < DNUM) ? d : 0;
        addr[k] = pb + (dd / 7) * 14 + (dd % 7);
    }

    float acc[13];
#pragma unroll
    for (int k = 0; k < 13; k++) acc[k] = 0.f;

    const float* __restrict__ qptr = Q + (size_t)(gy * WNUM + gx) * CMID;

    for (int c0 = 0; c0 < CMID; c0 += 16) {
#pragma unroll
        for (int i = 0; i < 4; i++) {
            int id = t + i * 256;
            if (id < 784) {
                int hp = id >> 2;
                int cv = id & 3;
                int hy = hp / 14, hx = hp - hy * 14;
                int sy = ty * 8 + hy - RAD;
                int sx = tx * 8 + hx - RAD;
                float4 v = make_float4(0.f, 0.f, 0.f, 0.f);
                if ((unsigned)sy < (unsigned)HNUM && (unsigned)sx < (unsigned)WNUM)
                    v = *(const float4*)(K + (size_t)(sy * WNUM + sx) * CMID + c0 + cv * 4);
                ks[cv * 4 + 0][hp] = v.x;
                ks[cv * 4 + 1][hp] = v.y;
                ks[cv * 4 + 2][hp] = v.z;
                ks[cv * 4 + 3][hp] = v.w;
            }
        }
        __syncthreads();

        float qr[16];
#pragma unroll
        for (int i = 0; i < 4; i++)
            *(float4*)&qr[i * 4] = *(const float4*)(qptr + c0 + i * 4);

#pragma unroll
        for (int cc = 0; cc < 16; cc++) {
            float qc = qr[cc];
#pragma unroll
            for (int k = 0; k < 13; k++)
                acc[k] += qc * ks[cc][addr[k]];
        }
        __syncthreads();
    }

    const int hw = gy * WNUM + gx;
#pragma unroll
    for (int k = 0; k < 13; k++) {
        int d = grp + 4 * k;
        if (d < DNUM)
            g_corr[((size_t)b * DNUM + d) * HW + hw] = acc[k];
    }
}

// ---------------------------------------------------------------
// K3: vol = Wv@corr + bv, geometry, softmax, du/dv/conf.
// 4 threads/pixel, 128-thread blocks (32 px) -> 784 blocks (was grid-limited
// at 392). Thread q owns logits [16q,16q+16), Wv rows padded to 64.
// ---------------------------------------------------------------
__global__ __launch_bounds__(128) void k_final(const float* __restrict__ P_cur,
                                               const float* __restrict__ P_rnd,
                                               const float* __restrict__ Wv,
                                               const float* __restrict__ bv,
                                               const float* __restrict__ gamma_p,
                                               float* __restrict__ out) {
    __shared__ float Wvt[49 * 64];     // [d][e], e padded to 64 (pad = 0)
    __shared__ float bvs[64];
    const int t = threadIdx.x;
    for (int id = t; id < 49 * 64; id += 128) {
        int d = id >> 6, e = id & 63;
        Wvt[id] = (e < 49) ? Wv[e * 49 + d] : 0.f;
    }
    if (t < 64) bvs[t] = (t < 49) ? bv[t] : -3.0e38f;
    __syncthreads();

    const int q  = t & 3;
    const int pl = t >> 2;                  // 0..31
    const int pixg = blockIdx.x * 32 + pl;
    const int b  = pixg / HW;
    const int hw = pixg - b * HW;
    const int h  = hw / WNUM;
    const int w  = hw - h * WNUM;
    const float gamma = *gamma_p;
    const int e0 = q * 16;

    const float* __restrict__ Pc = P_cur + (size_t)b * 3 * HW;
    const float* __restrict__ Pr = P_rnd + (size_t)b * 3 * HW;
    const float pcx = Pc[hw], pcy = Pc[HW + hw], pcz = Pc[2 * HW + hw];

    float l[16];
#pragma unroll
    for (int i = 0; i < 16; i++) {
        int e = e0 + i;
        if (e < 49) {
            int iy = e / 7, ix = e - iy * 7;
            int sy = h + iy - RAD, sx = w + ix - RAD;
            float prx = 0.f, pry = 0.f, prz = 0.f;
            if ((unsigned)sy < (unsigned)HNUM && (unsigned)sx < (unsigned)WNUM) {
                int o = sy * WNUM + sx;
                prx = Pr[o]; pry = Pr[HW + o]; prz = Pr[2 * HW + o];
            }
            float dx = pcx - prx, dy = pcy - pry, dz = pcz - prz;
            float ds = dx * dx + dy * dy + dz * dz;
            float dist = sqrtf(fmaxf(ds, 1e-12f));
            l[i] = bvs[e] + gamma * (-dist - 0.5f * fabsf(dz));
        } else {
            l[i] = -3.0e38f;
        }
    }

    const float* __restrict__ cb = g_corr + (size_t)b * DNUM * HW + hw;
    for (int d = 0; d < 49; d++) {
        float cd = cb[(size_t)d * HW];
        const float* wr = &Wvt[d * 64 + e0];
#pragma unroll
        for (int v4 = 0; v4 < 4; v4++) {
            float4 wv = *(const float4*)(wr + v4 * 4);
            l[v4 * 4 + 0] += wv.x * cd;
            l[v4 * 4 + 1] += wv.y * cd;
            l[v4 * 4 + 2] += wv.z * cd;
            l[v4 * 4 + 3] += wv.w * cd;
        }
    }

    float m = l[0];
#pragma unroll
    for (int i = 1; i < 16; i++) m = fmaxf(m, l[i]);
    m = fmaxf(m, __shfl_xor_sync(0xffffffffu, m, 1));
    m = fmaxf(m, __shfl_xor_sync(0xffffffffu, m, 2));

    float S = 0.f, du = 0.f, dv = 0.f;
#pragma unroll
    for (int i = 0; i < 16; i++) {
        int e = e0 + i;
        float ex = (e < 49) ? __expf(l[i] - m) : 0.f;
        S  += ex;
        du += ex * (float)(e % 7 - 3);
        dv += ex * (float)(e / 7 - 3);
    }
    S  += __shfl_xor_sync(0xffffffffu, S, 1);
    S  += __shfl_xor_sync(0xffffffffu, S, 2);
    du += __shfl_xor_sync(0xffffffffu, du, 1);
    du += __shfl_xor_sync(0xffffffffu, du, 2);
    dv += __shfl_xor_sync(0xffffffffu, dv, 1);
    dv += __shfl_xor_sync(0xffffffffu, dv, 2);

    if (q == 0) {
        float inv = 1.f / S;
        out[pixg]                 = du * inv;
        out[BNUM * HW + pixg]     = dv * inv;
        out[2 * BNUM * HW + pixg] = inv;   // conf = exp(m-m)/S
    }
}

// ---------------------------------------------------------------
extern "C" void kernel_launch(void* const* d_in, const int* in_sizes, int n_in,
                              void* d_out, int out_size) {
    const float* phi_cur = (const float*)d_in[0];
    const float* phi_rnd = (const float*)d_in[1];
    const float* P_cur   = (const float*)d_in[2];
    const float* P_rnd   = (const float*)d_in[3];
    const float* Wq      = (const float*)d_in[4];
    const float* Wk      = (const float*)d_in[5];
    const float* Wv      = (const float*)d_in[6];
    const float* bv      = (const float*)d_in[7];
    const float* gamma   = (const float*)d_in[8];
    float* out = (float*)d_out;

    cudaFuncSetAttribute(k_gemm, cudaFuncAttributeMaxDynamicSharedMemorySize, GEMM_SMEM);

    k_prep<<<128, 256>>>(Wq, Wk);
    k_gemm<<<dim3(HW / NT, BNUM, 2), 256, GEMM_SMEM>>>(phi_cur, phi_rnd);
    k_corr<<<dim3(WNUM / 8, HNUM / 8, BNUM), 256>>>();
    k_final<<<(BNUM * HW) / 32, 128>>>(P_cur, P_rnd, Wv, bv, gamma, out);
}